// round 9
// baseline (speedup 1.0000x reference)
#include <cuda_runtime.h>
#include <math_constants.h>

// Shapes
#define S_    1024
#define B_    256
#define N_    256
#define M_    512
#define E_    64
#define SM1   1023
#define CHUNK_LEN    64

// Scratch (static device memory)
__device__ float g_zcp [8 * N_ * B_];       // zc split-k partials [kc][b*256+n]
__device__ float g_cwT [M_ * N_];           // conv_w transposed: [j(512)][o(256)]
__device__ float g_w1zp[8 * E_ * B_];       // W1z split-k partials [(mc*64+e)*256+b]
__device__ float g_pm  [B_ * 2];            // per-(b,block) merged max
__device__ float g_pl  [B_ * 2];            // per-(b,block) merged sum
__device__ float g_pa2 [B_ * 2 * 512];      // per-(b,block) merged A (interleaved a0,a1)

// ---------------------------------------------------------------------------
// P1: fused prologue. 288 blocks, 256 threads.
// ---------------------------------------------------------------------------
__global__ __launch_bounds__(256) void p1_prologue(const float* __restrict__ D,
                                                   const float* __restrict__ z,
                                                   const float* __restrict__ convw,
                                                   const float* __restrict__ W1) {
    __shared__ float sbuf[64 * 17];
    const int tid = threadIdx.x;
    const int bid = blockIdx.x;

    if (bid < 128) {
        // ---- zc partials: zcp[kc][b][n16] = sum_{m in chunk} D[n][m] z[m][b]
        float (*sD)[17] = reinterpret_cast<float (*)[17]>(sbuf);
        const int nt = bid & 15, kc = bid >> 4;
        #pragma unroll
        for (int e = 0; e < 4; e++) {
            int idx = tid + e * 256;
            int nn = idx >> 6, mm = idx & 63;
            sD[mm][nn] = __ldg(D + (size_t)(nt * 16 + nn) * 512 + kc * 64 + mm);
        }
        __syncthreads();
        float acc[16];
        #pragma unroll
        for (int i = 0; i < 16; i++) acc[i] = 0.f;
        const int b = tid;
        #pragma unroll 8
        for (int mm = 0; mm < 64; mm++) {
            float zv = __ldg(z + (size_t)(kc * 64 + mm) * B_ + b);
            #pragma unroll
            for (int nn = 0; nn < 16; nn++) acc[nn] += sD[mm][nn] * zv;
        }
        float* dst = g_zcp + (size_t)kc * (N_ * B_) + (size_t)b * 256 + nt * 16;
        #pragma unroll
        for (int w = 0; w < 4; w++)
            reinterpret_cast<float4*>(dst)[w] =
                make_float4(acc[4*w], acc[4*w+1], acc[4*w+2], acc[4*w+3]);
    } else if (bid < 256) {
        // ---- transpose conv_w [o(256)][j(512)] -> g_cwT [j][o], 32x32 tile
        float (*st)[33] = reinterpret_cast<float (*)[33]>(sbuf);
        const int t = bid - 128;
        const int j0 = (t & 15) * 32, o0 = (t >> 4) * 32;
        const int tx = tid & 31, ty = tid >> 5;
        #pragma unroll
        for (int k = 0; k < 4; k++) {
            int row = ty + k * 8;
            st[row][tx] = __ldg(convw + (size_t)(o0 + row) * 512 + j0 + tx);
        }
        __syncthreads();
        #pragma unroll
        for (int k = 0; k < 4; k++) {
            int row = ty + k * 8;
            g_cwT[(size_t)(j0 + row) * 256 + o0 + tx] = st[tx][row];
        }
    } else {
        // ---- W1z partials: w1zp[mc][e][b] = sum_{m in chunk} W1[e][256+m] z[m][b]
        float (*sW)[64] = reinterpret_cast<float (*)[64]>(sbuf);
        const int w = bid - 256;
        const int et = w & 3, mc = w >> 2;
        {
            int idx = tid * 4;
            int e_l = idx >> 6, mm = idx & 63;
            float4 v = __ldg(reinterpret_cast<const float4*>(
                W1 + (size_t)(et * 16 + e_l) * 768 + 256 + mc * 64 + mm));
            sW[e_l][mm] = v.x; sW[e_l][mm+1] = v.y; sW[e_l][mm+2] = v.z; sW[e_l][mm+3] = v.w;
        }
        __syncthreads();
        float acc[16];
        #pragma unroll
        for (int i = 0; i < 16; i++) acc[i] = 0.f;
        const int b = tid;
        #pragma unroll 8
        for (int mm = 0; mm < 64; mm++) {
            float zv = __ldg(z + (size_t)(mc * 64 + mm) * B_ + b);
            #pragma unroll
            for (int e = 0; e < 16; e++) acc[e] += sW[e][mm] * zv;
        }
        #pragma unroll
        for (int e = 0; e < 16; e++)
            g_w1zp[(size_t)(mc * 64 + et * 16 + e) * 256 + b] = acc[e];
    }
}

// ---------------------------------------------------------------------------
// K1: main context pass with two-deep prefetch and block-level flash merge.
// grid (256, 2), 256 threads (8 warps, warp = 64-frame chunk).
// ---------------------------------------------------------------------------
__global__ __launch_bounds__(256) void k1_main(const float* __restrict__ ctx,
                                               const float* __restrict__ t1p) {
    __shared__ float sAcc[8][512];     // per-warp partial A, interleaved (a0,a1)
    __shared__ float sM[8], sL[8];

    const int b    = blockIdx.x;
    const int blk  = blockIdx.y;
    const int wid  = threadIdx.x >> 5;
    const int lane = threadIdx.x & 31;
    const int q    = blk * 8 + wid;
    const int s0   = q * CHUNK_LEN;
    const int s1   = min(s0 + CHUNK_LEN, SM1);

    const float neg_invt = -1.0f / fmaxf(fabsf(__ldg(t1p)), 1e-4f);

    // zc[b][lane*8..+8] = sum of 8 split-k partials (L2-resident, tiny)
    float zv[8];
    #pragma unroll
    for (int j = 0; j < 8; j++) zv[j] = 0.f;
    #pragma unroll
    for (int kc = 0; kc < 8; kc++) {
        const float4* p = reinterpret_cast<const float4*>(
            g_zcp + (size_t)kc * (N_ * B_) + (size_t)b * 256 + lane * 8);
        float4 x = p[0], y = p[1];
        zv[0] += x.x; zv[1] += x.y; zv[2] += x.z; zv[3] += x.w;
        zv[4] += y.x; zv[5] += y.y; zv[6] += y.z; zv[7] += y.w;
    }

    float c[8], cn[8], a0[8], a1[8];
    #pragma unroll
    for (int j = 0; j < 8; j++) { a0[j] = 0.f; a1[j] = 0.f; }
    float m = -CUDART_INF_F, l = 0.f;

    const float* base = ctx + ((size_t)s0 * B_ + b) * N_ + lane * 8;
    {
        const float4* r0 = reinterpret_cast<const float4*>(base);
        float4 x = __ldg(r0), y = __ldg(r0 + 1);
        c[0]=x.x; c[1]=x.y; c[2]=x.z; c[3]=x.w; c[4]=y.x; c[5]=y.y; c[6]=y.z; c[7]=y.w;
        const float4* r1 = reinterpret_cast<const float4*>(base + (size_t)(B_ * N_));
        float4 u = __ldg(r1), v = __ldg(r1 + 1);
        cn[0]=u.x; cn[1]=u.y; cn[2]=u.z; cn[3]=u.w; cn[4]=v.x; cn[5]=v.y; cn[6]=v.z; cn[7]=v.w;
    }

    for (int s = s0; s < s1; s++) {
        // prefetch row s+2 (clamped; 2 iterations ahead of its consumer)
        int sp = min(s + 2, SM1);   // <= 1023, always a valid row
        const float4* rn = reinterpret_cast<const float4*>(
            base + (size_t)(sp - s0) * (B_ * N_));
        float4 x = __ldg(rn), y = __ldg(rn + 1);

        float d = 0.f;
        #pragma unroll
        for (int j = 0; j < 8; j++) d += fabsf(c[j] - zv[j]);
        #pragma unroll
        for (int off = 16; off; off >>= 1)
            d += __shfl_xor_sync(0xffffffffu, d, off);

        float v = d * neg_invt;
        float w;
        if (v > m) {                       // warp-uniform
            float al = __expf(m - v);      // m=-inf -> 0 on first iter
            l = l * al + 1.f;
            #pragma unroll
            for (int j = 0; j < 8; j++) { a0[j] *= al; a1[j] *= al; }
            m = v; w = 1.f;
        } else {
            w = __expf(v - m);
            l += w;
        }
        #pragma unroll
        for (int j = 0; j < 8; j++) {
            a0[j] += w * c[j];
            a1[j] += w * cn[j];
            c[j] = cn[j];
        }
        cn[0]=x.x; cn[1]=x.y; cn[2]=x.z; cn[3]=x.w;
        cn[4]=y.x; cn[5]=y.y; cn[6]=y.z; cn[7]=y.w;
    }

    // ---- block-level flash merge of 8 warp partials ----
    if (lane == 0) { sM[wid] = m; sL[wid] = l; }
    #pragma unroll
    for (int j = 0; j < 8; j++) {
        sAcc[wid][lane * 16 + 2 * j]     = a0[j];   // n = lane*8+j -> pos 2n
        sAcc[wid][lane * 16 + 2 * j + 1] = a1[j];
    }
    __syncthreads();

    float M = -CUDART_INF_F;
    #pragma unroll
    for (int w = 0; w < 8; w++) M = fmaxf(M, sM[w]);
    float sc[8]; float L = 0.f;
    #pragma unroll
    for (int w = 0; w < 8; w++) { sc[w] = __expf(sM[w] - M); L += sL[w] * sc[w]; }

    // each thread combines 2 positions
    const int tid = threadIdx.x;
    float2 acc = make_float2(0.f, 0.f);
    #pragma unroll
    for (int w = 0; w < 8; w++) {
        float2 v2 = *reinterpret_cast<const float2*>(&sAcc[w][tid * 2]);
        acc.x += v2.x * sc[w];
        acc.y += v2.y * sc[w];
    }
    const int pidx = b * 2 + blk;
    reinterpret_cast<float2*>(g_pa2 + (size_t)pidx * 512)[tid] = acc;
    if (tid == 0) { g_pm[pidx] = M; g_pl[pidx] = L; }
}

// ---------------------------------------------------------------------------
// K2: merge 2 block-partials (L2) -> conv GEMM -> MLP -> softmax.
// 64 blocks x 4 b, 256 threads.
// ---------------------------------------------------------------------------
#define BNB 4
__global__ __launch_bounds__(256) void k2_epilogue(
        const float* __restrict__ convb, const float* __restrict__ W1,
        const float* __restrict__ W2,    const float* __restrict__ t2p,
        float* __restrict__ out) {
    __shared__ float sA[BNB][512];       // normalized A, interleaved
    __shared__ float sE[BNB][260];
    __shared__ float sScale[BNB][2];     // per-b normalized block scales (invL folded)
    __shared__ float sW1[64][33];
    __shared__ float sW2[64][65];
    __shared__ float sH[BNB][64];
    __shared__ float sRed[8], sRed2[8];

    const int tid = threadIdx.x;
    const int b0  = blockIdx.x * BNB;

    // step 1: per-b merge stats over the 2 block partials
    if (tid < BNB) {
        int b = b0 + tid;
        float m0 = g_pm[2*b], m1 = g_pm[2*b + 1];
        float M  = fmaxf(m0, m1);
        float s0 = __expf(m0 - M), s1 = __expf(m1 - M);
        float L  = g_pl[2*b] * s0 + g_pl[2*b + 1] * s1;
        float invL = 1.0f / L;
        sScale[tid][0] = s0 * invL;
        sScale[tid][1] = s1 * invL;
    }
    // stage W2 concurrently (coalesced)
    {
        int e_l = tid >> 2, off = (tid & 3) * 16;
        #pragma unroll
        for (int k = 0; k < 4; k++) {
            float4 v = __ldg(reinterpret_cast<const float4*>(W2 + e_l * 64 + off + k * 4));
            sW2[e_l][off + k*4] = v.x; sW2[e_l][off + k*4+1] = v.y;
            sW2[e_l][off + k*4+2] = v.z; sW2[e_l][off + k*4+3] = v.w;
        }
    }
    __syncthreads();

    // step 2: combine the 2 partials (g_pa2 is 1MB -> L2 resident), normalized
    #pragma unroll
    for (int bb = 0; bb < BNB; bb++) {
        int b = b0 + bb;
        float s0 = sScale[bb][0], s1 = sScale[bb][1];
        float2 p0 = reinterpret_cast<const float2*>(g_pa2 + (size_t)(2*b)     * 512)[tid];
        float2 p1 = reinterpret_cast<const float2*>(g_pa2 + (size_t)(2*b + 1) * 512)[tid];
        sA[bb][2*tid]     = p0.x * s0 + p1.x * s1;
        sA[bb][2*tid + 1] = p0.y * s0 + p1.y * s1;
    }
    __syncthreads();

    // step 3: conv GEMM, coalesced: emb[bb][o] = convb[o] + sum_j cwT[j][o]*sA[bb][j]
    {
        const int o = tid;
        float cb = __ldg(convb + o);
        float acc[BNB];
        #pragma unroll
        for (int bb = 0; bb < BNB; bb++) acc[bb] = cb;
        #pragma unroll 8
        for (int j = 0; j < 512; j++) {
            float w = g_cwT[(size_t)j * 256 + o];
            #pragma unroll
            for (int bb = 0; bb < BNB; bb++) acc[bb] += w * sA[bb][j];
        }
        #pragma unroll
        for (int bb = 0; bb < BNB; bb++) sE[bb][o] = acc[bb];
    }
    __syncthreads();

    // step 4: MLP layer 1 (+ReLU). thread = (bb, e); z-half precomputed
    {
        const int bb = tid >> 6, e = tid & 63, b = b0 + bb;
        float h = 0.f;
        #pragma unroll
        for (int mc = 0; mc < 8; mc++)
            h += g_w1zp[(size_t)(mc * 64 + e) * 256 + b];
        #pragma unroll 1
        for (int jc = 0; jc < 8; jc++) {
            {   // stage W1[e][jc*32 .. +32] for all 64 e (coalesced float4)
                int e_l = tid >> 2, part = (tid & 3) * 8;
                float4 v0 = __ldg(reinterpret_cast<const float4*>(
                    W1 + (size_t)e_l * 768 + jc * 32 + part));
                float4 v1 = __ldg(reinterpret_cast<const float4*>(
                    W1 + (size_t)e_l * 768 + jc * 32 + part + 4));
                sW1[e_l][part]   = v0.x; sW1[e_l][part+1] = v0.y;
                sW1[e_l][part+2] = v0.z; sW1[e_l][part+3] = v0.w;
                sW1[e_l][part+4] = v1.x; sW1[e_l][part+5] = v1.y;
                sW1[e_l][part+6] = v1.z; sW1[e_l][part+7] = v1.w;
            }
            __syncthreads();
            #pragma unroll
            for (int jj = 0; jj < 32; jj++)
                h += sW1[e][jj] * sE[bb][jc * 32 + jj];
            __syncthreads();
        }
        sH[bb][e] = fmaxf(h, 0.f);
    }
    __syncthreads();

    // step 5: layer 2 + softmax over E=64
    {
        const int bb = tid >> 6, e = tid & 63, b = b0 + bb;
        const int wd = tid >> 5, lane = tid & 31;
        float acc = 0.f;
        #pragma unroll
        for (int e2 = 0; e2 < 64; e2++) acc += sH[bb][e2] * sW2[e][e2];
        float t2 = fmaxf(fabsf(__ldg(t2p)), 1e-4f);
        float v = -acc / t2;

        float mx = v;
        #pragma unroll
        for (int off = 16; off; off >>= 1)
            mx = fmaxf(mx, __shfl_xor_sync(0xffffffffu, mx, off));
        if (lane == 0) sRed[wd] = mx;
        __syncthreads();
        mx = fmaxf(sRed[wd], sRed[wd ^ 1]);
        float ev = __expf(v - mx);
        float sm = ev;
        #pragma unroll
        for (int off = 16; off; off >>= 1)
            sm += __shfl_xor_sync(0xffffffffu, sm, off);
        if (lane == 0) sRed2[wd] = sm;
        __syncthreads();
        sm = sRed2[wd] + sRed2[wd ^ 1];
        out[(size_t)e * B_ + b] = ev / sm;
    }
}

// ---------------------------------------------------------------------------
extern "C" void kernel_launch(void* const* d_in, const int* in_sizes, int n_in,
                              void* d_out, int out_size) {
    const float* ctx   = (const float*)d_in[0];
    const float* z     = (const float*)d_in[1];
    const float* D     = (const float*)d_in[2];
    const float* convw = (const float*)d_in[3];
    const float* convb = (const float*)d_in[4];
    const float* W1    = (const float*)d_in[5];
    const float* W2    = (const float*)d_in[6];
    const float* t1    = (const float*)d_in[7];
    const float* t2    = (const float*)d_in[8];
    float* out = (float*)d_out;

    p1_prologue<<<288, 256>>>(D, z, convw, W1);
    k1_main<<<dim3(B_, 2), 256>>>(ctx, t1);
    k2_epilogue<<<64, 256>>>(convb, W1, W2, t2, out);
}

// round 11
// speedup vs baseline: 1.4070x; 1.4070x over previous
#include <cuda_runtime.h>
#include <math_constants.h>

// Shapes
#define S_    1024
#define B_    256
#define N_    256
#define M_    512
#define E_    64
#define SM1   1023
#define CHUNK_LEN    64

// Scratch (static device memory)
__device__ float g_zcp [8 * N_ * B_];       // zc split-k partials [kc][b*256+n]
__device__ float g_cwT [M_ * N_];           // conv_w transposed: [j(512)][o(256)]
__device__ float g_w1zp[8 * E_ * B_];       // W1z split-k partials [(mc*64+e)*256+b]
__device__ float g_pm  [B_ * 2];            // per-(b,block) merged max
__device__ float g_pl  [B_ * 2];            // per-(b,block) merged sum
__device__ float g_pa2 [B_ * 2 * 512];      // per-(b,block) merged A (interleaved a0,a1)

// ---------------------------------------------------------------------------
// P1: fused prologue. 288 blocks, 256 threads. (unchanged)
// ---------------------------------------------------------------------------
__global__ __launch_bounds__(256) void p1_prologue(const float* __restrict__ D,
                                                   const float* __restrict__ z,
                                                   const float* __restrict__ convw,
                                                   const float* __restrict__ W1) {
    __shared__ float sbuf[64 * 17];
    const int tid = threadIdx.x;
    const int bid = blockIdx.x;

    if (bid < 128) {
        // ---- zc partials: zcp[kc][b][n16] = sum_{m in chunk} D[n][m] z[m][b]
        float (*sD)[17] = reinterpret_cast<float (*)[17]>(sbuf);
        const int nt = bid & 15, kc = bid >> 4;
        #pragma unroll
        for (int e = 0; e < 4; e++) {
            int idx = tid + e * 256;
            int nn = idx >> 6, mm = idx & 63;
            sD[mm][nn] = __ldg(D + (size_t)(nt * 16 + nn) * 512 + kc * 64 + mm);
        }
        __syncthreads();
        float acc[16];
        #pragma unroll
        for (int i = 0; i < 16; i++) acc[i] = 0.f;
        const int b = tid;
        #pragma unroll 8
        for (int mm = 0; mm < 64; mm++) {
            float zv = __ldg(z + (size_t)(kc * 64 + mm) * B_ + b);
            #pragma unroll
            for (int nn = 0; nn < 16; nn++) acc[nn] += sD[mm][nn] * zv;
        }
        float* dst = g_zcp + (size_t)kc * (N_ * B_) + (size_t)b * 256 + nt * 16;
        #pragma unroll
        for (int w = 0; w < 4; w++)
            reinterpret_cast<float4*>(dst)[w] =
                make_float4(acc[4*w], acc[4*w+1], acc[4*w+2], acc[4*w+3]);
    } else if (bid < 256) {
        // ---- transpose conv_w [o(256)][j(512)] -> g_cwT [j][o], 32x32 tile
        float (*st)[33] = reinterpret_cast<float (*)[33]>(sbuf);
        const int t = bid - 128;
        const int j0 = (t & 15) * 32, o0 = (t >> 4) * 32;
        const int tx = tid & 31, ty = tid >> 5;
        #pragma unroll
        for (int k = 0; k < 4; k++) {
            int row = ty + k * 8;
            st[row][tx] = __ldg(convw + (size_t)(o0 + row) * 512 + j0 + tx);
        }
        __syncthreads();
        #pragma unroll
        for (int k = 0; k < 4; k++) {
            int row = ty + k * 8;
            g_cwT[(size_t)(j0 + row) * 256 + o0 + tx] = st[tx][row];
        }
    } else {
        // ---- W1z partials: w1zp[mc][e][b] = sum_{m in chunk} W1[e][256+m] z[m][b]
        float (*sW)[64] = reinterpret_cast<float (*)[64]>(sbuf);
        const int w = bid - 256;
        const int et = w & 3, mc = w >> 2;
        {
            int idx = tid * 4;
            int e_l = idx >> 6, mm = idx & 63;
            float4 v = __ldg(reinterpret_cast<const float4*>(
                W1 + (size_t)(et * 16 + e_l) * 768 + 256 + mc * 64 + mm));
            sW[e_l][mm] = v.x; sW[e_l][mm+1] = v.y; sW[e_l][mm+2] = v.z; sW[e_l][mm+3] = v.w;
        }
        __syncthreads();
        float acc[16];
        #pragma unroll
        for (int i = 0; i < 16; i++) acc[i] = 0.f;
        const int b = tid;
        #pragma unroll 8
        for (int mm = 0; mm < 64; mm++) {
            float zv = __ldg(z + (size_t)(mc * 64 + mm) * B_ + b);
            #pragma unroll
            for (int e = 0; e < 16; e++) acc[e] += sW[e][mm] * zv;
        }
        #pragma unroll
        for (int e = 0; e < 16; e++)
            g_w1zp[(size_t)(mc * 64 + et * 16 + e) * 256 + b] = acc[e];
    }
}

// ---------------------------------------------------------------------------
// K1: main context pass. Inner loop reverted to the R4 (fast) 1-deep prefetch
// form; block-level flash merge of the 8 warp partials kept.
// grid (256, 2), 256 threads (8 warps, warp = 64-frame chunk).
// ---------------------------------------------------------------------------
__global__ __launch_bounds__(256) void k1_main(const float* __restrict__ ctx,
                                               const float* __restrict__ t1p) {
    __shared__ float sAcc[8][512];     // per-warp partial A, interleaved (a0,a1)
    __shared__ float sM[8], sL[8];

    const int b    = blockIdx.x;
    const int blk  = blockIdx.y;
    const int wid  = threadIdx.x >> 5;
    const int lane = threadIdx.x & 31;
    const int q    = blk * 8 + wid;
    const int s0   = q * CHUNK_LEN;
    const int s1   = min(s0 + CHUNK_LEN, SM1);

    const float neg_invt = -1.0f / fmaxf(fabsf(__ldg(t1p)), 1e-4f);

    // zc[b][lane*8..+8] = sum of 8 split-k partials (L2-resident, tiny)
    float zv[8];
    #pragma unroll
    for (int j = 0; j < 8; j++) zv[j] = 0.f;
    #pragma unroll
    for (int kc = 0; kc < 8; kc++) {
        const float4* p = reinterpret_cast<const float4*>(
            g_zcp + (size_t)kc * (N_ * B_) + (size_t)b * 256 + lane * 8);
        float4 x = p[0], y = p[1];
        zv[0] += x.x; zv[1] += x.y; zv[2] += x.z; zv[3] += x.w;
        zv[4] += y.x; zv[5] += y.y; zv[6] += y.z; zv[7] += y.w;
    }

    float c[8], a0[8], a1[8];
    #pragma unroll
    for (int j = 0; j < 8; j++) { a0[j] = 0.f; a1[j] = 0.f; }
    float m = -CUDART_INF_F, l = 0.f;

    const float* base = ctx + ((size_t)s0 * B_ + b) * N_ + lane * 8;
    {
        const float4* r4 = reinterpret_cast<const float4*>(base);
        float4 x = __ldg(r4), y = __ldg(r4 + 1);
        c[0]=x.x; c[1]=x.y; c[2]=x.z; c[3]=x.w;
        c[4]=y.x; c[5]=y.y; c[6]=y.z; c[7]=y.w;
    }

    for (int s = s0; s < s1; s++) {
        // load row s+1 (<= 1023, always valid) — consumed this iteration (a1)
        const float4* rn = reinterpret_cast<const float4*>(
            base + (size_t)(s - s0 + 1) * (B_ * N_));
        float4 x = __ldg(rn), y = __ldg(rn + 1);
        float cn[8] = {x.x, x.y, x.z, x.w, y.x, y.y, y.z, y.w};

        float d = 0.f;
        #pragma unroll
        for (int j = 0; j < 8; j++) d += fabsf(c[j] - zv[j]);
        #pragma unroll
        for (int off = 16; off; off >>= 1)
            d += __shfl_xor_sync(0xffffffffu, d, off);

        float v = d * neg_invt;
        float w;
        if (v > m) {                       // warp-uniform
            float al = __expf(m - v);      // m=-inf -> 0 on first iter
            l = l * al + 1.f;
            #pragma unroll
            for (int j = 0; j < 8; j++) { a0[j] *= al; a1[j] *= al; }
            m = v; w = 1.f;
        } else {
            w = __expf(v - m);
            l += w;
        }
        #pragma unroll
        for (int j = 0; j < 8; j++) {
            a0[j] += w * c[j];
            a1[j] += w * cn[j];
            c[j] = cn[j];
        }
    }

    // ---- block-level flash merge of 8 warp partials ----
    if (lane == 0) { sM[wid] = m; sL[wid] = l; }
    #pragma unroll
    for (int j = 0; j < 8; j++) {
        sAcc[wid][lane * 16 + 2 * j]     = a0[j];   // n = lane*8+j -> pos 2n
        sAcc[wid][lane * 16 + 2 * j + 1] = a1[j];
    }
    __syncthreads();

    float M = -CUDART_INF_F;
    #pragma unroll
    for (int w = 0; w < 8; w++) M = fmaxf(M, sM[w]);
    float sc[8]; float L = 0.f;
    #pragma unroll
    for (int w = 0; w < 8; w++) { sc[w] = __expf(sM[w] - M); L += sL[w] * sc[w]; }

    // each thread combines 2 positions
    const int tid = threadIdx.x;
    float2 acc = make_float2(0.f, 0.f);
    #pragma unroll
    for (int w = 0; w < 8; w++) {
        float2 v2 = *reinterpret_cast<const float2*>(&sAcc[w][tid * 2]);
        acc.x += v2.x * sc[w];
        acc.y += v2.y * sc[w];
    }
    const int pidx = b * 2 + blk;
    reinterpret_cast<float2*>(g_pa2 + (size_t)pidx * 512)[tid] = acc;
    if (tid == 0) { g_pm[pidx] = M; g_pl[pidx] = L; }
}

// ---------------------------------------------------------------------------
// K2: merge 2 block-partials (L2) -> conv GEMM -> MLP -> softmax.
// 64 blocks x 4 b, 256 threads. (unchanged from R9)
// ---------------------------------------------------------------------------
#define BNB 4
__global__ __launch_bounds__(256) void k2_epilogue(
        const float* __restrict__ convb, const float* __restrict__ W1,
        const float* __restrict__ W2,    const float* __restrict__ t2p,
        float* __restrict__ out) {
    __shared__ float sA[BNB][512];       // normalized A, interleaved
    __shared__ float sE[BNB][260];
    __shared__ float sScale[BNB][2];     // per-b normalized block scales (invL folded)
    __shared__ float sW1[64][33];
    __shared__ float sW2[64][65];
    __shared__ float sH[BNB][64];
    __shared__ float sRed[8], sRed2[8];

    const int tid = threadIdx.x;
    const int b0  = blockIdx.x * BNB;

    // step 1: per-b merge stats over the 2 block partials
    if (tid < BNB) {
        int b = b0 + tid;
        float m0 = g_pm[2*b], m1 = g_pm[2*b + 1];
        float M  = fmaxf(m0, m1);
        float s0 = __expf(m0 - M), s1 = __expf(m1 - M);
        float L  = g_pl[2*b] * s0 + g_pl[2*b + 1] * s1;
        float invL = 1.0f / L;
        sScale[tid][0] = s0 * invL;
        sScale[tid][1] = s1 * invL;
    }
    // stage W2 concurrently (coalesced)
    {
        int e_l = tid >> 2, off = (tid & 3) * 16;
        #pragma unroll
        for (int k = 0; k < 4; k++) {
            float4 v = __ldg(reinterpret_cast<const float4*>(W2 + e_l * 64 + off + k * 4));
            sW2[e_l][off + k*4] = v.x; sW2[e_l][off + k*4+1] = v.y;
            sW2[e_l][off + k*4+2] = v.z; sW2[e_l][off + k*4+3] = v.w;
        }
    }
    __syncthreads();

    // step 2: combine the 2 partials (g_pa2 is 1MB -> L2 resident), normalized
    #pragma unroll
    for (int bb = 0; bb < BNB; bb++) {
        int b = b0 + bb;
        float s0 = sScale[bb][0], s1 = sScale[bb][1];
        float2 p0 = reinterpret_cast<const float2*>(g_pa2 + (size_t)(2*b)     * 512)[tid];
        float2 p1 = reinterpret_cast<const float2*>(g_pa2 + (size_t)(2*b + 1) * 512)[tid];
        sA[bb][2*tid]     = p0.x * s0 + p1.x * s1;
        sA[bb][2*tid + 1] = p0.y * s0 + p1.y * s1;
    }
    __syncthreads();

    // step 3: conv GEMM, coalesced: emb[bb][o] = convb[o] + sum_j cwT[j][o]*sA[bb][j]
    {
        const int o = tid;
        float cb = __ldg(convb + o);
        float acc[BNB];
        #pragma unroll
        for (int bb = 0; bb < BNB; bb++) acc[bb] = cb;
        #pragma unroll 8
        for (int j = 0; j < 512; j++) {
            float w = g_cwT[(size_t)j * 256 + o];
            #pragma unroll
            for (int bb = 0; bb < BNB; bb++) acc[bb] += w * sA[bb][j];
        }
        #pragma unroll
        for (int bb = 0; bb < BNB; bb++) sE[bb][o] = acc[bb];
    }
    __syncthreads();

    // step 4: MLP layer 1 (+ReLU). thread = (bb, e); z-half precomputed
    {
        const int bb = tid >> 6, e = tid & 63, b = b0 + bb;
        float h = 0.f;
        #pragma unroll
        for (int mc = 0; mc < 8; mc++)
            h += g_w1zp[(size_t)(mc * 64 + e) * 256 + b];
        #pragma unroll 1
        for (int jc = 0; jc < 8; jc++) {
            {   // stage W1[e][jc*32 .. +32] for all 64 e (coalesced float4)
                int e_l = tid >> 2, part = (tid & 3) * 8;
                float4 v0 = __ldg(reinterpret_cast<const float4*>(
                    W1 + (size_t)e_l * 768 + jc * 32 + part));
                float4 v1 = __ldg(reinterpret_cast<const float4*>(
                    W1 + (size_t)e_l * 768 + jc * 32 + part + 4));
                sW1[e_l][part]   = v0.x; sW1[e_l][part+1] = v0.y;
                sW1[e_l][part+2] = v0.z; sW1[e_l][part+3] = v0.w;
                sW1[e_l][part+4] = v1.x; sW1[e_l][part+5] = v1.y;
                sW1[e_l][part+6] = v1.z; sW1[e_l][part+7] = v1.w;
            }
            __syncthreads();
            #pragma unroll
            for (int jj = 0; jj < 32; jj++)
                h += sW1[e][jj] * sE[bb][jc * 32 + jj];
            __syncthreads();
        }
        sH[bb][e] = fmaxf(h, 0.f);
    }
    __syncthreads();

    // step 5: layer 2 + softmax over E=64
    {
        const int bb = tid >> 6, e = tid & 63, b = b0 + bb;
        const int wd = tid >> 5, lane = tid & 31;
        float acc = 0.f;
        #pragma unroll
        for (int e2 = 0; e2 < 64; e2++) acc += sH[bb][e2] * sW2[e][e2];
        float t2 = fmaxf(fabsf(__ldg(t2p)), 1e-4f);
        float v = -acc / t2;

        float mx = v;
        #pragma unroll
        for (int off = 16; off; off >>= 1)
            mx = fmaxf(mx, __shfl_xor_sync(0xffffffffu, mx, off));
        if (lane == 0) sRed[wd] = mx;
        __syncthreads();
        mx = fmaxf(sRed[wd], sRed[wd ^ 1]);
        float ev = __expf(v - mx);
        float sm = ev;
        #pragma unroll
        for (int off = 16; off; off >>= 1)
            sm += __shfl_xor_sync(0xffffffffu, sm, off);
        if (lane == 0) sRed2[wd] = sm;
        __syncthreads();
        sm = sRed2[wd] + sRed2[wd ^ 1];
        out[(size_t)e * B_ + b] = ev / sm;
    }
}

// ---------------------------------------------------------------------------
extern "C" void kernel_launch(void* const* d_in, const int* in_sizes, int n_in,
                              void* d_out, int out_size) {
    const float* ctx   = (const float*)d_in[0];
    const float* z     = (const float*)d_in[1];
    const float* D     = (const float*)d_in[2];
    const float* convw = (const float*)d_in[3];
    const float* convb = (const float*)d_in[4];
    const float* W1    = (const float*)d_in[5];
    const float* W2    = (const float*)d_in[6];
    const float* t1    = (const float*)d_in[7];
    const float* t2    = (const float*)d_in[8];
    float* out = (float*)d_out;

    p1_prologue<<<288, 256>>>(D, z, convw, W1);
    k1_main<<<dim3(B_, 2), 256>>>(ctx, t1);
    k2_epilogue<<<64, 256>>>(convb, W1, W2, t2, out);
}

// round 13
// speedup vs baseline: 1.4658x; 1.0418x over previous
#include <cuda_runtime.h>
#include <math_constants.h>

// Shapes
#define S_    1024
#define B_    256
#define N_    256
#define M_    512
#define E_    64
#define SM1   1023
#define CHUNK_LEN 128          // rows per warp (8 warps * 128 = 1024 >= 1023)

// Scratch (static device memory)
__device__ float g_zcp [8 * N_ * B_];       // zc split-k partials [kc][b*256+n]
__device__ float g_cwT [M_ * N_];           // conv_w transposed: [j(512)][o(256)]
__device__ float g_w1zp[8 * E_ * B_];       // W1z split-k partials [(mc*64+e)*256+b]
__device__ float g_pl  [B_];                // per-b softmax denominator
__device__ float g_pa2 [B_ * 512];          // per-b merged A (interleaved a0,a1), unnormalized

// ---------------------------------------------------------------------------
// P1: fused prologue. 288 blocks, 256 threads. (unchanged)
// ---------------------------------------------------------------------------
__global__ __launch_bounds__(256) void p1_prologue(const float* __restrict__ D,
                                                   const float* __restrict__ z,
                                                   const float* __restrict__ convw,
                                                   const float* __restrict__ W1) {
    __shared__ float sbuf[64 * 17];
    const int tid = threadIdx.x;
    const int bid = blockIdx.x;

    if (bid < 128) {
        float (*sD)[17] = reinterpret_cast<float (*)[17]>(sbuf);
        const int nt = bid & 15, kc = bid >> 4;
        #pragma unroll
        for (int e = 0; e < 4; e++) {
            int idx = tid + e * 256;
            int nn = idx >> 6, mm = idx & 63;
            sD[mm][nn] = __ldg(D + (size_t)(nt * 16 + nn) * 512 + kc * 64 + mm);
        }
        __syncthreads();
        float acc[16];
        #pragma unroll
        for (int i = 0; i < 16; i++) acc[i] = 0.f;
        const int b = tid;
        #pragma unroll 8
        for (int mm = 0; mm < 64; mm++) {
            float zv = __ldg(z + (size_t)(kc * 64 + mm) * B_ + b);
            #pragma unroll
            for (int nn = 0; nn < 16; nn++) acc[nn] += sD[mm][nn] * zv;
        }
        float* dst = g_zcp + (size_t)kc * (N_ * B_) + (size_t)b * 256 + nt * 16;
        #pragma unroll
        for (int w = 0; w < 4; w++)
            reinterpret_cast<float4*>(dst)[w] =
                make_float4(acc[4*w], acc[4*w+1], acc[4*w+2], acc[4*w+3]);
    } else if (bid < 256) {
        float (*st)[33] = reinterpret_cast<float (*)[33]>(sbuf);
        const int t = bid - 128;
        const int j0 = (t & 15) * 32, o0 = (t >> 4) * 32;
        const int tx = tid & 31, ty = tid >> 5;
        #pragma unroll
        for (int k = 0; k < 4; k++) {
            int row = ty + k * 8;
            st[row][tx] = __ldg(convw + (size_t)(o0 + row) * 512 + j0 + tx);
        }
        __syncthreads();
        #pragma unroll
        for (int k = 0; k < 4; k++) {
            int row = ty + k * 8;
            g_cwT[(size_t)(j0 + row) * 256 + o0 + tx] = st[tx][row];
        }
    } else {
        float (*sW)[64] = reinterpret_cast<float (*)[64]>(sbuf);
        const int w = bid - 256;
        const int et = w & 3, mc = w >> 2;
        {
            int idx = tid * 4;
            int e_l = idx >> 6, mm = idx & 63;
            float4 v = __ldg(reinterpret_cast<const float4*>(
                W1 + (size_t)(et * 16 + e_l) * 768 + 256 + mc * 64 + mm));
            sW[e_l][mm] = v.x; sW[e_l][mm+1] = v.y; sW[e_l][mm+2] = v.z; sW[e_l][mm+3] = v.w;
        }
        __syncthreads();
        float acc[16];
        #pragma unroll
        for (int i = 0; i < 16; i++) acc[i] = 0.f;
        const int b = tid;
        #pragma unroll 8
        for (int mm = 0; mm < 64; mm++) {
            float zv = __ldg(z + (size_t)(mc * 64 + mm) * B_ + b);
            #pragma unroll
            for (int e = 0; e < 16; e++) acc[e] += sW[e][mm] * zv;
        }
        #pragma unroll
        for (int e = 0; e < 16; e++)
            g_w1zp[(size_t)(mc * 64 + et * 16 + e) * 256 + b] = acc[e];
    }
}

// ---------------------------------------------------------------------------
// K1: context pass, 4-row-batched online softmax.
// grid (256), 256 threads (8 warps, warp = 128-row chunk). One partial per b.
// ---------------------------------------------------------------------------
__global__ __launch_bounds__(256) void k1_main(const float* __restrict__ ctx,
                                               const float* __restrict__ t1p) {
    __shared__ float sAcc[8][512];
    __shared__ float sM[8], sL[8];

    const int b    = blockIdx.x;
    const int wid  = threadIdx.x >> 5;
    const int lane = threadIdx.x & 31;
    const int s0   = wid * CHUNK_LEN;
    const int s1   = min(s0 + CHUNK_LEN, SM1);

    const float neg_invt = -1.0f / fmaxf(fabsf(__ldg(t1p)), 1e-4f);

    // zc[b][lane*8..+8] = sum of 8 split-k partials (L2-resident)
    float zv[8];
    #pragma unroll
    for (int j = 0; j < 8; j++) zv[j] = 0.f;
    #pragma unroll
    for (int kc = 0; kc < 8; kc++) {
        const float4* p = reinterpret_cast<const float4*>(
            g_zcp + (size_t)kc * (N_ * B_) + (size_t)b * 256 + lane * 8);
        float4 x = p[0], y = p[1];
        zv[0] += x.x; zv[1] += x.y; zv[2] += x.z; zv[3] += x.w;
        zv[4] += y.x; zv[5] += y.y; zv[6] += y.z; zv[7] += y.w;
    }

    float c[8], a0[8], a1[8];
    #pragma unroll
    for (int j = 0; j < 8; j++) { a0[j] = 0.f; a1[j] = 0.f; }
    float m = -CUDART_INF_F, l = 0.f;

    const float* base = ctx + ((size_t)s0 * B_ + b) * N_ + lane * 8;
    {
        const float4* r4 = reinterpret_cast<const float4*>(base);
        float4 x = __ldg(r4), y = __ldg(r4 + 1);
        c[0]=x.x; c[1]=x.y; c[2]=x.z; c[3]=x.w;
        c[4]=y.x; c[5]=y.y; c[6]=y.z; c[7]=y.w;
    }

    int s = s0;
    // ---- batched main loop: 4 rows per iteration ----
    for (; s + 4 <= s1; s += 4) {
        float r[4][8];
        #pragma unroll
        for (int k = 0; k < 4; k++) {        // rows s+1..s+4 (<=1023, valid)
            const float4* rp = reinterpret_cast<const float4*>(
                base + (size_t)(s - s0 + 1 + k) * (B_ * N_));
            float4 x = __ldg(rp), y = __ldg(rp + 1);
            r[k][0]=x.x; r[k][1]=x.y; r[k][2]=x.z; r[k][3]=x.w;
            r[k][4]=y.x; r[k][5]=y.y; r[k][6]=y.z; r[k][7]=y.w;
        }

        // 4 partial L1 distances (rows s..s+3), then 4 interleaved butterflies
        float d0 = 0.f, d1 = 0.f, d2 = 0.f, d3 = 0.f;
        #pragma unroll
        for (int j = 0; j < 8; j++) {
            d0 += fabsf(c[j]    - zv[j]);
            d1 += fabsf(r[0][j] - zv[j]);
            d2 += fabsf(r[1][j] - zv[j]);
            d3 += fabsf(r[2][j] - zv[j]);
        }
        #pragma unroll
        for (int off = 16; off; off >>= 1) {
            d0 += __shfl_xor_sync(0xffffffffu, d0, off);
            d1 += __shfl_xor_sync(0xffffffffu, d1, off);
            d2 += __shfl_xor_sync(0xffffffffu, d2, off);
            d3 += __shfl_xor_sync(0xffffffffu, d3, off);
        }

        float v0 = d0 * neg_invt, v1 = d1 * neg_invt;
        float v2 = d2 * neg_invt, v3 = d3 * neg_invt;
        float Mn = fmaxf(m, fmaxf(fmaxf(v0, v1), fmaxf(v2, v3)));
        float al = __expf(m - Mn);           // m=-inf on first batch -> 0
        float w0 = __expf(v0 - Mn), w1 = __expf(v1 - Mn);
        float w2 = __expf(v2 - Mn), w3 = __expf(v3 - Mn);
        l = l * al + (w0 + w1 + w2 + w3);
        m = Mn;

        #pragma unroll
        for (int j = 0; j < 8; j++) {
            a0[j] = a0[j]*al + w0*c[j]    + w1*r[0][j] + w2*r[1][j] + w3*r[2][j];
            a1[j] = a1[j]*al + w0*r[0][j] + w1*r[1][j] + w2*r[2][j] + w3*r[3][j];
            c[j]  = r[3][j];
        }
    }
    // ---- remainder rows (last warp only: up to 3) ----
    for (; s < s1; s++) {
        const float4* rn = reinterpret_cast<const float4*>(
            base + (size_t)(s - s0 + 1) * (B_ * N_));
        float4 x = __ldg(rn), y = __ldg(rn + 1);
        float cn[8] = {x.x, x.y, x.z, x.w, y.x, y.y, y.z, y.w};

        float d = 0.f;
        #pragma unroll
        for (int j = 0; j < 8; j++) d += fabsf(c[j] - zv[j]);
        #pragma unroll
        for (int off = 16; off; off >>= 1)
            d += __shfl_xor_sync(0xffffffffu, d, off);

        float v = d * neg_invt;
        float Mn = fmaxf(m, v);
        float al = __expf(m - Mn);
        float w  = __expf(v - Mn);
        l = l * al + w;
        m = Mn;
        #pragma unroll
        for (int j = 0; j < 8; j++) {
            a0[j] = a0[j]*al + w * c[j];
            a1[j] = a1[j]*al + w * cn[j];
            c[j] = cn[j];
        }
    }

    // ---- block-level flash merge of 8 warp partials -> single per-b partial ----
    if (lane == 0) { sM[wid] = m; sL[wid] = l; }
    #pragma unroll
    for (int j = 0; j < 8; j++) {
        sAcc[wid][lane * 16 + 2 * j]     = a0[j];
        sAcc[wid][lane * 16 + 2 * j + 1] = a1[j];
    }
    __syncthreads();

    float M = -CUDART_INF_F;
    #pragma unroll
    for (int w = 0; w < 8; w++) M = fmaxf(M, sM[w]);
    float sc[8]; float L = 0.f;
    #pragma unroll
    for (int w = 0; w < 8; w++) { sc[w] = __expf(sM[w] - M); L += sL[w] * sc[w]; }

    const int tid = threadIdx.x;
    float2 acc = make_float2(0.f, 0.f);
    #pragma unroll
    for (int w = 0; w < 8; w++) {
        float2 v2 = *reinterpret_cast<const float2*>(&sAcc[w][tid * 2]);
        acc.x += v2.x * sc[w];
        acc.y += v2.y * sc[w];
    }
    reinterpret_cast<float2*>(g_pa2 + (size_t)b * 512)[tid] = acc;
    if (tid == 0) g_pl[b] = L;
}

// ---------------------------------------------------------------------------
// K2: normalize per-b partial (L2) -> conv GEMM -> MLP -> softmax.
// 64 blocks x 4 b, 256 threads.
// ---------------------------------------------------------------------------
#define BNB 4
__global__ __launch_bounds__(256) void k2_epilogue(
        const float* __restrict__ convb, const float* __restrict__ W1,
        const float* __restrict__ W2,    const float* __restrict__ t2p,
        float* __restrict__ out) {
    __shared__ float sA[BNB][512];
    __shared__ float sE[BNB][260];
    __shared__ float sInvL[BNB];
    __shared__ float sW1[64][33];
    __shared__ float sW2[64][65];
    __shared__ float sH[BNB][64];
    __shared__ float sRed[8], sRed2[8];

    const int tid = threadIdx.x;
    const int b0  = blockIdx.x * BNB;

    if (tid < BNB) sInvL[tid] = 1.0f / g_pl[b0 + tid];
    {   // stage W2 (coalesced)
        int e_l = tid >> 2, off = (tid & 3) * 16;
        #pragma unroll
        for (int k = 0; k < 4; k++) {
            float4 v = __ldg(reinterpret_cast<const float4*>(W2 + e_l * 64 + off + k * 4));
            sW2[e_l][off + k*4] = v.x; sW2[e_l][off + k*4+1] = v.y;
            sW2[e_l][off + k*4+2] = v.z; sW2[e_l][off + k*4+3] = v.w;
        }
    }
    __syncthreads();

    // normalize per-b accumulator (g_pa2 is 512KB -> L2 resident)
    #pragma unroll
    for (int bb = 0; bb < BNB; bb++) {
        int b = b0 + bb;
        float invL = sInvL[bb];
        float2 p = reinterpret_cast<const float2*>(g_pa2 + (size_t)b * 512)[tid];
        sA[bb][2*tid]     = p.x * invL;
        sA[bb][2*tid + 1] = p.y * invL;
    }
    __syncthreads();

    // conv GEMM, coalesced
    {
        const int o = tid;
        float cb = __ldg(convb + o);
        float acc[BNB];
        #pragma unroll
        for (int bb = 0; bb < BNB; bb++) acc[bb] = cb;
        #pragma unroll 8
        for (int j = 0; j < 512; j++) {
            float w = g_cwT[(size_t)j * 256 + o];
            #pragma unroll
            for (int bb = 0; bb < BNB; bb++) acc[bb] += w * sA[bb][j];
        }
        #pragma unroll
        for (int bb = 0; bb < BNB; bb++) sE[bb][o] = acc[bb];
    }
    __syncthreads();

    // MLP layer 1 (+ReLU); z-half precomputed in g_w1zp
    {
        const int bb = tid >> 6, e = tid & 63, b = b0 + bb;
        float h = 0.f;
        #pragma unroll
        for (int mc = 0; mc < 8; mc++)
            h += g_w1zp[(size_t)(mc * 64 + e) * 256 + b];
        #pragma unroll 1
        for (int jc = 0; jc < 8; jc++) {
            {
                int e_l = tid >> 2, part = (tid & 3) * 8;
                float4 v0 = __ldg(reinterpret_cast<const float4*>(
                    W1 + (size_t)e_l * 768 + jc * 32 + part));
                float4 v1 = __ldg(reinterpret_cast<const float4*>(
                    W1 + (size_t)e_l * 768 + jc * 32 + part + 4));
                sW1[e_l][part]   = v0.x; sW1[e_l][part+1] = v0.y;
                sW1[e_l][part+2] = v0.z; sW1[e_l][part+3] = v0.w;
                sW1[e_l][part+4] = v1.x; sW1[e_l][part+5] = v1.y;
                sW1[e_l][part+6] = v1.z; sW1[e_l][part+7] = v1.w;
            }
            __syncthreads();
            #pragma unroll
            for (int jj = 0; jj < 32; jj++)
                h += sW1[e][jj] * sE[bb][jc * 32 + jj];
            __syncthreads();
        }
        sH[bb][e] = fmaxf(h, 0.f);
    }
    __syncthreads();

    // layer 2 + softmax over E=64
    {
        const int bb = tid >> 6, e = tid & 63, b = b0 + bb;
        const int wd = tid >> 5, lane = tid & 31;
        float acc = 0.f;
        #pragma unroll
        for (int e2 = 0; e2 < 64; e2++) acc += sH[bb][e2] * sW2[e][e2];
        float t2 = fmaxf(fabsf(__ldg(t2p)), 1e-4f);
        float v = -acc / t2;

        float mx = v;
        #pragma unroll
        for (int off = 16; off; off >>= 1)
            mx = fmaxf(mx, __shfl_xor_sync(0xffffffffu, mx, off));
        if (lane == 0) sRed[wd] = mx;
        __syncthreads();
        mx = fmaxf(sRed[wd], sRed[wd ^ 1]);
        float ev = __expf(v - mx);
        float sm = ev;
        #pragma unroll
        for (int off = 16; off; off >>= 1)
            sm += __shfl_xor_sync(0xffffffffu, sm, off);
        if (lane == 0) sRed2[wd] = sm;
        __syncthreads();
        sm = sRed2[wd] + sRed2[wd ^ 1];
        out[(size_t)e * B_ + b] = ev / sm;
    }
}

// ---------------------------------------------------------------------------
extern "C" void kernel_launch(void* const* d_in, const int* in_sizes, int n_in,
                              void* d_out, int out_size) {
    const float* ctx   = (const float*)d_in[0];
    const float* z     = (const float*)d_in[1];
    const float* D     = (const float*)d_in[2];
    const float* convw = (const float*)d_in[3];
    const float* convb = (const float*)d_in[4];
    const float* W1    = (const float*)d_in[5];
    const float* W2    = (const float*)d_in[6];
    const float* t1    = (const float*)d_in[7];
    const float* t2    = (const float*)d_in[8];
    float* out = (float*)d_out;

    p1_prologue<<<288, 256>>>(D, z, convw, W1);
    k1_main<<<B_, 256>>>(ctx, t1);
    k2_epilogue<<<64, 256>>>(convb, W1, W2, t2, out);
}